// round 16
// baseline (speedup 1.0000x reference)
#include <cuda_runtime.h>
#include <cuda_bf16.h>
#include <math.h>
#include <stdint.h>

#define BATCH 4
#define NQ    2048
#define NR    16384
#define DIM   64
#define KNN   16

#define TQ 128
#define TR 128
#define QHS 72            // bf16 row stride (64 + 8 pad) = 144 B, conflict-free
#define RHS 72

#define RCHUNKS 16
#define RCHUNK  (NR / RCHUNKS)      // 1024 refs per block
#define RTILES  (RCHUNK / TR)       // 8 tiles
#define TSEL  8                      // per-(thread,qrow) approx top-T
#define NSLICE 8                     // slices per (query, chunk)
#define NCAND 32                     // approx candidates rescored exactly

#define FULLM 0xffffffffu
#define INF_F __int_as_float(0x7f800000)

// Scratch (allocation-free rule: __device__ globals)
__device__ float g_r2[BATCH * NR];
__device__ float g_q2[BATCH * NQ];
// approx partial keys: [b][q][chunk][slice][TSEL] u64 -> 67 MB
__device__ unsigned long long g_part[(size_t)BATCH * NQ * RCHUNKS * NSLICE * TSEL];

// ---------------------------------------------------------------------------
// Kernel 1: squared norms (bit-exact XLA-style warp tree; validated)
// ---------------------------------------------------------------------------
__global__ void norms_kernel(const float* __restrict__ ref,
                             const float* __restrict__ query) {
    int warp = (blockIdx.x * blockDim.x + threadIdx.x) >> 5;
    int lane = threadIdx.x & 31;
    int total = BATCH * NR + BATCH * NQ;
    if (warp >= total) return;

    const float* row;
    float* out;
    if (warp < BATCH * NR) {
        row = ref + (size_t)warp * DIM;
        out = g_r2 + warp;
    } else {
        int u = warp - BATCH * NR;
        row = query + (size_t)u * DIM;
        out = g_q2 + u;
    }

    float x0 = row[lane];
    float x1 = row[lane + 32];
    float s = __fadd_rn(__fmul_rn(x0, x0), __fmul_rn(x1, x1));
#pragma unroll
    for (int off = 16; off; off >>= 1)
        s = __fadd_rn(s, __shfl_down_sync(FULLM, s, off));
    if (lane == 0) *out = s;
}

// ---------------------------------------------------------------------------
// mma.sync m16n8k16 bf16 (A row-major, B col-major, fp32 accum) — validated
// ---------------------------------------------------------------------------
__device__ __forceinline__ void mma_bf16(float c[4],
                                         const uint32_t a[4],
                                         uint32_t b0, uint32_t b1) {
    asm volatile(
        "mma.sync.aligned.m16n8k16.row.col.f32.bf16.bf16.f32 "
        "{%0,%1,%2,%3}, {%4,%5,%6,%7}, {%8,%9}, {%0,%1,%2,%3};"
        : "+f"(c[0]), "+f"(c[1]), "+f"(c[2]), "+f"(c[3])
        : "r"(a[0]), "r"(a[1]), "r"(a[2]), "r"(a[3]), "r"(b0), "r"(b1));
}

__device__ __forceinline__ void ldsm_x4(uint32_t r[4], uint32_t saddr) {
    asm volatile(
        "ldmatrix.sync.aligned.m8n8.x4.shared.b16 {%0,%1,%2,%3}, [%4];"
        : "=r"(r[0]), "=r"(r[1]), "=r"(r[2]), "=r"(r[3]) : "r"(saddr));
}

// Branch-free sorted insert into ascending top-TSEL (val,idx) lists.
__device__ __forceinline__ void insert8(float* dl, int* il, float dz, int iz) {
    if (dz < dl[TSEL - 1]) {
#pragma unroll
        for (int j = TSEL - 1; j >= 1; j--) {
            bool pA = dz < dl[j - 1];
            bool pB = dz < dl[j];
            il[j] = pA ? il[j - 1] : (pB ? iz : il[j]);
            dl[j] = pA ? dl[j - 1] : (pB ? dz : dl[j]);
        }
        bool p0 = dz < dl[0];
        il[0] = p0 ? iz : il[0];
        dl[0] = p0 ? dz : dl[0];
    }
}

// monotonic float -> u32 (total order incl. negatives)
__device__ __forceinline__ unsigned fmono(float f) {
    unsigned u = __float_as_uint(f);
    return u ^ (((unsigned)((int)u >> 31)) | 0x80000000u);
}

// ---------------------------------------------------------------------------
// Kernel 2 (FUSED): 512 threads, 16 warps (8 m-groups x 2 n-halves).
// HMMA candidate pass; selection with tile-level min prefilter: one guard per
// (thread, q-row) per tile instead of 32 divergent insert guards.
// ---------------------------------------------------------------------------
__global__ __launch_bounds__(512, 1) void fused_kernel(const float* __restrict__ ref,
                                                       const float* __restrict__ query) {
    extern __shared__ char smraw[];
    uint16_t* Qh  = (uint16_t*)smraw;                              // [TQ][QHS]
    uint16_t* Rh  = (uint16_t*)(smraw + TQ * QHS * 2);             // 2x [TR][RHS]
    float*    r2s = (float*)(smraw + TQ * QHS * 2 + 2 * TR * RHS * 2); // [RCHUNK]

    int b   = blockIdx.z;
    int q0  = blockIdx.y * TQ;
    int cnk = blockIdx.x;
    int rbase = cnk * RCHUNK;
    int tid = threadIdx.x;

    int frow = tid >> 4;          // 0..31
    int fd   = (tid & 15) * 4;

    // Q tile -> bf16 smem
    const float* qg = query + ((size_t)b * NQ + q0) * DIM;
#pragma unroll
    for (int it = 0; it < 4; ++it) {
        int row = frow + it * 32;
        float4 v = *(const float4*)(qg + (size_t)row * DIM + fd);
        __nv_bfloat162 p0 = __floats2bfloat162_rn(v.x, v.y);
        __nv_bfloat162 p1 = __floats2bfloat162_rn(v.z, v.w);
        uint2 u;
        u.x = *(uint32_t*)&p0;
        u.y = *(uint32_t*)&p1;
        *(uint2*)&Qh[row * QHS + fd] = u;
    }
    // stage r2 chunk
    {
        float2 v = *(const float2*)(g_r2 + b * NR + rbase + tid * 2);
        *(float2*)(r2s + tid * 2) = v;
    }

    // preload tile 0 into Rh buffer 0
    {
        const float* rg = ref + ((size_t)b * NR + rbase) * DIM;
#pragma unroll
        for (int it = 0; it < 4; ++it) {
            int row = frow + it * 32;
            float4 v = *(const float4*)(rg + (size_t)row * DIM + fd);
            __nv_bfloat162 p0 = __floats2bfloat162_rn(v.x, v.y);
            __nv_bfloat162 p1 = __floats2bfloat162_rn(v.z, v.w);
            uint2 u;
            u.x = *(uint32_t*)&p0;
            u.y = *(uint32_t*)&p1;
            *(uint2*)&Rh[row * RHS + fd] = u;
        }
    }
    __syncthreads();

    int warp = tid >> 5;
    int lane = tid & 31;
    int g  = lane >> 2;
    int t2 = (lane & 3) * 2;
    int wq = (warp >> 1) * 16;    // m-group base (8 groups)
    int wr = (warp & 1) * 64;     // n-half base

    uint32_t qh_base = (uint32_t)__cvta_generic_to_shared(Qh);
    uint32_t rh_base = (uint32_t)__cvta_generic_to_shared(Rh);
    uint32_t a_addr0 = qh_base +
        (((wq + (lane & 15)) * QHS + (lane >> 4) * 8) << 1);
    int sel = lane >> 3;
    uint32_t b_off0 = (((wr + (sel >> 1) * 8 + (lane & 7)) * RHS
                        + (sel & 1) * 8) << 1);

    float dl0[TSEL], dl1[TSEL];
    int   il0[TSEL], il1[TSEL];
#pragma unroll
    for (int j = 0; j < TSEL; j++) {
        dl0[j] = INF_F; dl1[j] = INF_F; il0[j] = 0; il1[j] = 0;
    }

    for (int t = 0; t < RTILES; t++) {
        int r0 = rbase + t * TR;
        uint32_t cur = rh_base + (uint32_t)((t & 1) * TR * RHS * 2);
        uint16_t* nxt = Rh + ((t + 1) & 1) * TR * RHS;

        // prefetch next tile (LDG only; consumed after MMA)
        float4 pre[4];
        if (t < RTILES - 1) {
            const float* rg = ref + ((size_t)b * NR + r0 + TR) * DIM;
#pragma unroll
            for (int it = 0; it < 4; ++it)
                pre[it] = *(const float4*)(rg + (size_t)(frow + it * 32) * DIM + fd);
        }

        float c[8][4];
#pragma unroll
        for (int nt = 0; nt < 8; nt++)
#pragma unroll
            for (int e = 0; e < 4; e++) c[nt][e] = 0.f;

#pragma unroll
        for (int ks = 0; ks < 4; ks++) {
            uint32_t a[4];
            ldsm_x4(a, a_addr0 + (ks * 16 << 1));
#pragma unroll
            for (int p = 0; p < 4; p++) {
                uint32_t bb[4];
                ldsm_x4(bb, cur + b_off0
                            + (uint32_t)(((p * 16 * RHS) + ks * 16) << 1));
                mma_bf16(c[2 * p],     a, bb[0], bb[1]);
                mma_bf16(c[2 * p + 1], a, bb[2], bb[3]);
            }
        }

        // ---- selection with tile-level min prefilter ----
        // pass 1: v = r2 - 2*dot (order == d2), fold per-list tile minima
        float vmin0 = INF_F, vmin1 = INF_F;
#pragma unroll
        for (int nt = 0; nt < 8; nt++) {
            int rc = t * TR + wr + nt * 8 + t2;
            float rA = r2s[rc];
            float rB = r2s[rc + 1];
            float v0 = __fmaf_rn(-2.f, c[nt][0], rA);
            float v1 = __fmaf_rn(-2.f, c[nt][1], rB);
            float v2 = __fmaf_rn(-2.f, c[nt][2], rA);
            float v3 = __fmaf_rn(-2.f, c[nt][3], rB);
            vmin0 = fminf(vmin0, fminf(v0, v1));
            vmin1 = fminf(vmin1, fminf(v2, v3));
        }
        // pass 2 (rare): recompute identical values from live fragments, insert
        if (vmin0 < dl0[TSEL - 1]) {
#pragma unroll
            for (int nt = 0; nt < 8; nt++) {
                int rc = t * TR + wr + nt * 8 + t2;
                int iA = r0 + wr + nt * 8 + t2;
                insert8(dl0, il0, __fmaf_rn(-2.f, c[nt][0], r2s[rc]), iA);
                insert8(dl0, il0, __fmaf_rn(-2.f, c[nt][1], r2s[rc + 1]), iA + 1);
            }
        }
        if (vmin1 < dl1[TSEL - 1]) {
#pragma unroll
            for (int nt = 0; nt < 8; nt++) {
                int rc = t * TR + wr + nt * 8 + t2;
                int iA = r0 + wr + nt * 8 + t2;
                insert8(dl1, il1, __fmaf_rn(-2.f, c[nt][2], r2s[rc]), iA);
                insert8(dl1, il1, __fmaf_rn(-2.f, c[nt][3], r2s[rc + 1]), iA + 1);
            }
        }

        // convert + store prefetched tile into alternate buffer
        if (t < RTILES - 1) {
#pragma unroll
            for (int it = 0; it < 4; ++it) {
                int row = frow + it * 32;
                __nv_bfloat162 p0 = __floats2bfloat162_rn(pre[it].x, pre[it].y);
                __nv_bfloat162 p1 = __floats2bfloat162_rn(pre[it].z, pre[it].w);
                uint2 u;
                u.x = *(uint32_t*)&p0;
                u.y = *(uint32_t*)&p1;
                *(uint2*)&nxt[row * RHS + fd] = u;
            }
        }
        __syncthreads();   // STS visible; all ldmatrix of cur done
    }

    // write partial lists: slice = n-half*4 + lane%4, keys = mono(v)<<32 | idx
    int slice = (warp & 1) * 4 + (lane & 3);
    {
        int q = q0 + wq + g;
        unsigned long long* dst = g_part +
            ((((size_t)(b * NQ + q)) * RCHUNKS + cnk) * NSLICE + slice) * TSEL;
#pragma unroll
        for (int j = 0; j < TSEL; j++)
            dst[j] = ((unsigned long long)fmono(dl0[j]) << 32) | (unsigned)il0[j];
    }
    {
        int q = q0 + wq + g + 8;
        unsigned long long* dst = g_part +
            ((((size_t)(b * NQ + q)) * RCHUNKS + cnk) * NSLICE + slice) * TSEL;
#pragma unroll
        for (int j = 0; j < TSEL; j++)
            dst[j] = ((unsigned long long)fmono(dl1[j]) << 32) | (unsigned)il1[j];
    }
}

// ---------------------------------------------------------------------------
// Kernel 3: merge 1024 approx keys/query -> approx top-32 -> EXACT rescore
// (validated sequential-k FMA chain + exact epilogue) -> exact top-16 out.
// Warp per query.
// ---------------------------------------------------------------------------
__global__ __launch_bounds__(256) void merge_kernel(const float* __restrict__ ref,
                                                    const float* __restrict__ query,
                                                    float* __restrict__ outD,
                                                    float* __restrict__ outI) {
    __shared__ float qs[8][DIM];

    int gwarp = (blockIdx.x * 256 + threadIdx.x) >> 5;
    int w     = (threadIdx.x >> 5) & 7;
    int lane  = threadIdx.x & 31;
    int b = gwarp / NQ;
    int q = gwarp % NQ;

    const float* qrow = query + ((size_t)b * NQ + q) * DIM;
    {
        float2 v = *(const float2*)(qrow + lane * 2);
        qs[w][lane * 2 + 0] = v.x;
        qs[w][lane * 2 + 1] = v.y;
    }
    __syncwarp();

    // gather 1024 approx keys -> per-lane sorted top-16 (u64 total order)
    const unsigned long long* src =
        g_part + (size_t)gwarp * RCHUNKS * NSLICE * TSEL;
    unsigned long long key[KNN];
#pragma unroll
    for (int j = 0; j < KNN; j++) key[j] = ~0ull;
#pragma unroll 8
    for (int i = 0; i < 32; i++) {
        unsigned long long kk = src[i * 32 + lane];
        if (kk < key[KNN - 1]) {
#pragma unroll
            for (int j = 0; j < KNN; j++) {
                if (kk < key[j]) {
                    unsigned long long tt = key[j]; key[j] = kk; kk = tt;
                }
            }
        }
    }

    // extract approx top-32; candidate r lands in lane r
    unsigned long long cand = ~0ull;
    for (int r = 0; r < NCAND; r++) {
        unsigned long long m = key[0];
#pragma unroll
        for (int off = 16; off; off >>= 1) {
            unsigned long long o = __shfl_xor_sync(FULLM, m, off);
            if (o < m) m = o;
        }
        if (key[0] == m) {   // unique winner pops
#pragma unroll
            for (int j = 0; j < KNN - 1; j++) key[j] = key[j + 1];
            key[KNN - 1] = ~0ull;
        }
        if (lane == r) cand = m;
    }
    int cidx = (int)(unsigned)(cand & 0xffffffffull);

    // exact rescore (bit-identical to validated pipeline)
    const float* rrow = ref + ((size_t)b * NR + cidx) * DIM;
    float dot = 0.f;
#pragma unroll
    for (int k4 = 0; k4 < DIM / 4; k4++) {
        float4 rv = *(const float4*)(rrow + k4 * 4);
        dot = __fmaf_rn(qs[w][k4 * 4 + 0], rv.x, dot);
        dot = __fmaf_rn(qs[w][k4 * 4 + 1], rv.y, dot);
        dot = __fmaf_rn(qs[w][k4 * 4 + 2], rv.z, dot);
        dot = __fmaf_rn(qs[w][k4 * 4 + 3], rv.w, dot);
    }
    float q2v = g_q2[b * NQ + q];
    float r2v = g_r2[b * NR + cidx];
    float d2 = fmaxf(__fmaf_rn(-2.f, dot, __fadd_rn(q2v, r2v)), 0.f);
    unsigned long long ekey =
        ((unsigned long long)__float_as_uint(d2) << 32) | (unsigned)cidx;

    float* Do = outD + (size_t)gwarp * KNN;
    float* Io = outI + (size_t)gwarp * KNN;

    for (int k = 0; k < KNN; k++) {
        unsigned long long m = ekey;
#pragma unroll
        for (int off = 16; off; off >>= 1) {
            unsigned long long o = __shfl_xor_sync(FULLM, m, off);
            if (o < m) m = o;
        }
        if (ekey == m) ekey = ~0ull;   // winner retires
        if (lane == 0) {
            Do[k] = sqrtf(__uint_as_float((unsigned)(m >> 32)));
            Io[k] = (float)(unsigned)(m & 0xffffffffull);
        }
    }
}

// ---------------------------------------------------------------------------
extern "C" void kernel_launch(void* const* d_in, const int* in_sizes, int n_in,
                              void* d_out, int out_size) {
    const float* ref   = (const float*)d_in[0];   // [B, NR, DIM]
    const float* query = (const float*)d_in[1];   // [B, NQ, DIM]

    float* outD = (float*)d_out;
    float* outI = outD + (size_t)BATCH * NQ * KNN;

    static const int smem_bytes =
        TQ * QHS * 2 + 2 * TR * RHS * 2 + RCHUNK * 4;  // 59392
    cudaFuncSetAttribute(fused_kernel,
                         cudaFuncAttributeMaxDynamicSharedMemorySize, smem_bytes);

    int n_rows = BATCH * NR + BATCH * NQ;
    int n_thr  = n_rows * 32;
    norms_kernel<<<(n_thr + 255) / 256, 256>>>(ref, query);

    dim3 g(RCHUNKS, NQ / TQ, BATCH);   // (16, 16, 4) = 1024 blocks
    fused_kernel<<<g, 512, smem_bytes>>>(ref, query);

    merge_kernel<<<(BATCH * NQ * 32) / 256, 256>>>(ref, query, outD, outI);
}